// round 12
// baseline (speedup 1.0000x reference)
#include <cuda_runtime.h>
#include <cstdint>

// Fixed problem shape.
#define BB 8
#define QQ 900
#define KK 1203
#define NN 100
#define ROW_BYTES (KK * 4)                 // 4812
#define TOT_F4 ((BB * QQ * KK) / 4)        // 2,165,400 float4 in logits
#define WARPS 8
#define THREADS (WARPS * 32)               // 256
#define BLOCKS (BB * QQ / WARPS)           // 900, warp <-> row

// cost[b,q,n] = 2*focal_cls + 5*L1 - 2*GIoU
// Sequential-sweep gather: each warp streams its logits row with coalesced
// LDG.128 (DRAM sees a pure sequential stream), then gathers the 100 labeled
// columns from L1/L2. An asm xor dependency orders gathers after the sweep so
// no random request reaches DRAM. No smem staging, no barriers.
__global__ void __launch_bounds__(THREADS) matcher_cost_kernel(
    const float*  __restrict__ logits,   // (B,Q,K)
    const float4* __restrict__ pboxes,   // (B,Q,4)
    const int*    __restrict__ labels,   // (B,N)
    const float4* __restrict__ tboxes,   // (B,N,4)
    float* __restrict__ out)             // (B,Q,N)
{
    const int tid  = threadIdx.x;
    const int w    = tid >> 5;
    const int lane = tid & 31;

    const int  row  = blockIdx.x * WARPS + w;     // global row in [0, 7200)
    const long base = (long)row * ROW_BYTES;      // byte offset of row
    const int  b    = row / QQ;
    const int  bn0  = b * NN;

    // ---- sequential sweep: 10 coalesced float4 loads covering the row ----
    const float4* g4 = (const float4*)logits;     // tensor base is 16B-aligned
    const long f40 = base >> 4;                   // first float4 covering row
    float4 v[10];
    #pragma unroll
    for (int i = 0; i < 10; i++) {
        long idx = f40 + lane + i * 32;           // 320 float4 >= 302 needed
        idx = min(idx, (long)(TOT_F4 - 1));       // tail clamp (harmless re-read)
        v[i] = __ldg(g4 + idx);
    }

    // ---- order the gather after the sweep: dep == 0, data-dependent on v[9] ----
    uint32_t dep;
    asm volatile("xor.b32 %0, %1, %1;" : "=r"(dep) : "r"(__float_as_int(v[9].x)));

    // ---- labels (tiny, L2-hot), made dependent on sweep completion ----
    int labv[4];
    #pragma unroll
    for (int i = 0; i < 4; i++) {
        int n  = lane + i * 32;
        int nn = min(n, NN - 1);
        int l  = __ldg(labels + bn0 + nn);
        labv[i] = min(max(l, 0), KK - 1) + (int)dep;
    }

    const float* lrow = logits + (long)row * KK;

    // ---- gathers: L1/L2 hits (row just swept) ----
    float xv[4];
    #pragma unroll
    for (int i = 0; i < 4; i++)
        xv[i] = __ldg(lrow + labv[i]);

    // keep the sweep loads alive (no arithmetic, no DCE)
    #pragma unroll
    for (int i = 0; i < 9; i++)
        asm volatile("" :: "f"(v[i].x), "f"(v[i].y), "f"(v[i].z), "f"(v[i].w));
    asm volatile("" :: "f"(v[9].y), "f"(v[9].z), "f"(v[9].w));

    // ---- per-row geometry ----
    const float4 pb = __ldg(pboxes + row);
    const float px0 = pb.x - 0.5f * pb.z, px1 = pb.x + 0.5f * pb.z;
    const float py0 = pb.y - 0.5f * pb.w, py1 = pb.y + 0.5f * pb.w;
    const float area1 = pb.z * pb.w;
    float* const orow = out + (long)row * NN;

    #pragma unroll
    for (int i = 0; i < 4; i++) {
        int n = lane + i * 32;
        if (n < NN) {
            float x = xv[i];

            // focal class cost (3 MUFU)
            float e  = __expf(-x);
            float sg = 1.0f + e;
            float p  = __fdividef(1.0f, sg);
            float L  = __logf(sg);
            float logp   = fmaxf(-L,     -18.420681f);
            float log1mp = fmaxf(-x - L, -18.420681f);
            float omp = 1.0f - p;
            float cls = -0.25f * omp * omp * logp + 0.75f * p * p * log1mp;

            // L1 box cost
            float4 tb = __ldg(tboxes + bn0 + n);
            float l1 = fabsf(pb.x - tb.x) + fabsf(pb.y - tb.y)
                     + fabsf(pb.z - tb.z) + fabsf(pb.w - tb.w);

            // GIoU (1 MUFU)
            float tx0 = tb.x - 0.5f * tb.z, tx1 = tb.x + 0.5f * tb.z;
            float ty0 = tb.y - 0.5f * tb.w, ty1 = tb.y + 0.5f * tb.w;
            float area2 = tb.z * tb.w;
            float wi = fmaxf(fminf(px1, tx1) - fmaxf(px0, tx0), 0.0f);
            float hi = fmaxf(fminf(py1, ty1) - fmaxf(py0, ty0), 0.0f);
            float inter = wi * hi;
            float uni   = area1 + area2 - inter;
            float wc = fmaxf(px1, tx1) - fminf(px0, tx0);
            float hc = fmaxf(py1, ty1) - fminf(py0, ty0);
            float ac = wc * hc;
            float num  = ac * (inter - uni) + uni * uni;
            float giou = num * __fdividef(1.0f, uni * ac);

            orow[n] = 2.0f * cls + 5.0f * l1 - 2.0f * giou;
        }
    }
}

extern "C" void kernel_launch(void* const* d_in, const int* in_sizes, int n_in,
                              void* d_out, int out_size)
{
    const float*  logits = (const float*)d_in[0];
    const float4* pboxes = (const float4*)d_in[1];
    const int*    labels = (const int*)d_in[2];
    const float4* tboxes = (const float4*)d_in[3];
    float* out = (float*)d_out;

    matcher_cost_kernel<<<BLOCKS, THREADS>>>(logits, pboxes, labels, tboxes, out);
}

// round 13
// speedup vs baseline: 1.0331x; 1.0331x over previous
#include <cuda_runtime.h>

// Fixed problem shape.
#define BB 8
#define QQ 900
#define KK 1203
#define NN 100
#define NQUAD (NN / 4)                    // 25
#define HALFQ (QQ / 2)                    // 450 row-pairs per batch
#define PAIRS_PER_BLK 10                  // 10 pairs * 25 quads = 250 threads
#define THREADS (PAIRS_PER_BLK * NQUAD)   // 250
#define BLKX (HALFQ / PAIRS_PER_BLK)      // 45

// cost[b,q,n] = 2*focal_cls + 5*L1 - 2*GIoU
// Champion gather (row-pairing, 8 outputs/thread) + per-block SMEM staging of
// batch metadata (clamped labels, target xyxy/area/box).
__global__ void __launch_bounds__(THREADS) matcher_cost_kernel(
    const float*  __restrict__ logits,   // (B,Q,K)
    const float4* __restrict__ pboxes,   // (B,Q,4)
    const int*    __restrict__ labels,   // (B,N)
    const float4* __restrict__ tboxes,   // (B,N,4)
    float4* __restrict__ out4)           // (B,Q,N) as float4
{
    __shared__ int    s_lab[NN];          // clamped labels
    __shared__ float4 s_tb[NN];           // cxcywh
    __shared__ float4 s_txy[NN];          // xyxy
    __shared__ float  s_ta[NN];           // areas

    const int b   = blockIdx.y;
    const int tid = threadIdx.x;

    // ---- stage batch metadata (once per block) ----
    if (tid < NN) {
        s_lab[tid] = min(max(labels[b * NN + tid], 0), KK - 1);
        float4 tb = tboxes[b * NN + tid];
        s_tb[tid] = tb;
        float4 xy;
        xy.x = tb.x - 0.5f * tb.z;
        xy.y = tb.y - 0.5f * tb.w;
        xy.z = tb.x + 0.5f * tb.z;
        xy.w = tb.y + 0.5f * tb.w;
        s_txy[tid] = xy;
        s_ta[tid]  = tb.z * tb.w;
    }
    __syncthreads();

    const int quad = tid % NQUAD;                          // n-quad
    const int pr   = blockIdx.x * PAIRS_PER_BLK + tid / NQUAD;  // pair in batch
    const long bq0 = (long)b * QQ + 2 * pr;                // first row of pair
    const int  n0  = quad * 4;

    // ---- labels from smem (short dep chain), 8 gathers front-batched ----
    const int l0 = s_lab[n0 + 0];
    const int l1i = s_lab[n0 + 1];
    const int l2 = s_lab[n0 + 2];
    const int l3 = s_lab[n0 + 3];

    const float* lrowA = logits + bq0 * KK;
    const float* lrowB = lrowA + KK;

    float xs[2][4];
    xs[0][0] = __ldg(lrowA + l0);  xs[0][1] = __ldg(lrowA + l1i);
    xs[0][2] = __ldg(lrowA + l2);  xs[0][3] = __ldg(lrowA + l3);
    xs[1][0] = __ldg(lrowB + l0);  xs[1][1] = __ldg(lrowB + l1i);
    xs[1][2] = __ldg(lrowB + l2);  xs[1][3] = __ldg(lrowB + l3);

    const float4 pbA = __ldg(pboxes + bq0);
    const float4 pbB = __ldg(pboxes + bq0 + 1);

    // ---- target geometry from smem (shared by both rows) ----
    float4 tbs[4], txy[4];
    float  ta[4];
    #pragma unroll
    for (int i = 0; i < 4; i++) {
        tbs[i] = s_tb[n0 + i];
        txy[i] = s_txy[n0 + i];
        ta[i]  = s_ta[n0 + i];
    }

    const float4 pbs[2] = {pbA, pbB};

    #pragma unroll
    for (int rr = 0; rr < 2; rr++) {
        const float4 pb = pbs[rr];
        const float px0 = pb.x - 0.5f * pb.z, px1 = pb.x + 0.5f * pb.z;
        const float py0 = pb.y - 0.5f * pb.w, py1 = pb.y + 0.5f * pb.w;
        const float area1 = pb.z * pb.w;

        float4 res;
        float* resp = &res.x;

        #pragma unroll
        for (int i = 0; i < 4; i++) {
            float x = xs[rr][i];

            // focal class cost (3 MUFU)
            float e  = __expf(-x);
            float sg = 1.0f + e;
            float p  = __fdividef(1.0f, sg);
            float L  = __logf(sg);
            float logp   = fmaxf(-L,     -18.420681f);
            float log1mp = fmaxf(-x - L, -18.420681f);
            float omp = 1.0f - p;
            float cls = -0.25f * omp * omp * logp + 0.75f * p * p * log1mp;

            // L1 box cost
            float l1 = fabsf(pb.x - tbs[i].x) + fabsf(pb.y - tbs[i].y)
                     + fabsf(pb.z - tbs[i].z) + fabsf(pb.w - tbs[i].w);

            // GIoU (1 MUFU)
            float wi = fmaxf(fminf(px1, txy[i].z) - fmaxf(px0, txy[i].x), 0.0f);
            float hi = fmaxf(fminf(py1, txy[i].w) - fmaxf(py0, txy[i].y), 0.0f);
            float inter = wi * hi;
            float uni   = area1 + ta[i] - inter;
            float wc = fmaxf(px1, txy[i].z) - fminf(px0, txy[i].x);
            float hc = fmaxf(py1, txy[i].w) - fminf(py0, txy[i].y);
            float ac = wc * hc;
            float num  = ac * (inter - uni) + uni * uni;
            float giou = num * __fdividef(1.0f, uni * ac);

            resp[i] = 2.0f * cls + 5.0f * l1 - 2.0f * giou;
        }

        out4[(bq0 + rr) * NQUAD + quad] = res;   // STG.128 coalesced
    }
}

extern "C" void kernel_launch(void* const* d_in, const int* in_sizes, int n_in,
                              void* d_out, int out_size)
{
    const float*  logits = (const float*)d_in[0];
    const float4* pboxes = (const float4*)d_in[1];
    const int*    labels = (const int*)d_in[2];
    const float4* tboxes = (const float4*)d_in[3];
    float4* out4 = (float4*)d_out;

    dim3 grid(BLKX, BB);    // (45, 8) = 360 blocks x 250 threads
    matcher_cost_kernel<<<grid, THREADS>>>(logits, pboxes, labels, tboxes, out4);
}

// round 14
// speedup vs baseline: 1.0369x; 1.0037x over previous
#include <cuda_runtime.h>

// Fixed problem shape.
#define BB 8
#define QQ 900
#define KK 1203
#define NN 100
#define NQUAD (NN / 4)                    // 25
#define TRIQ (QQ / 3)                     // 300 row-triples per batch
#define TOTALT (BB * TRIQ * NQUAD)        // 60000 threads, 12 outputs each

// cost[b,q,n] = 2*focal_cls + 5*L1 - 2*GIoU
// One thread: the same n-quad of THREE adjacent rows (3r..3r+2) of one batch.
// Labels + target boxes shared across the 3 rows; 12 independent gathers in
// flight per thread.
__global__ void __launch_bounds__(128) matcher_cost_kernel(
    const float*  __restrict__ logits,   // (B,Q,K)
    const float4* __restrict__ pboxes,   // (B,Q,4)
    const int4*   __restrict__ labels4,  // (B,N) as int4
    const float4* __restrict__ tboxes,   // (B,N,4)
    float4* __restrict__ out4)           // (B,Q,N) as float4
{
    int gid = blockIdx.x * blockDim.x + threadIdx.x;
    if (gid >= TOTALT) return;

    const int quad = gid % NQUAD;         // n-quad index
    const int tidx = gid / NQUAD;         // triple index (b*300 + r)
    const int b    = tidx / TRIQ;
    const int r    = tidx - b * TRIQ;
    const long bq0 = (long)b * QQ + 3 * r;   // first row of triple

    // ---- shared-per-triple loads ----
    int4 lab4 = __ldg(labels4 + b * NQUAD + quad);
    const int l0 = min(max(lab4.x, 0), KK - 1);
    const int l1i = min(max(lab4.y, 0), KK - 1);
    const int l2 = min(max(lab4.z, 0), KK - 1);
    const int l3 = min(max(lab4.w, 0), KK - 1);

    const float* lrowA = logits + bq0 * KK;
    const float* lrowB = lrowA + KK;
    const float* lrowC = lrowB + KK;

    // 12 independent gathers, front-batched
    float xs[3][4];
    xs[0][0] = __ldg(lrowA + l0);  xs[0][1] = __ldg(lrowA + l1i);
    xs[0][2] = __ldg(lrowA + l2);  xs[0][3] = __ldg(lrowA + l3);
    xs[1][0] = __ldg(lrowB + l0);  xs[1][1] = __ldg(lrowB + l1i);
    xs[1][2] = __ldg(lrowB + l2);  xs[1][3] = __ldg(lrowB + l3);
    xs[2][0] = __ldg(lrowC + l0);  xs[2][1] = __ldg(lrowC + l1i);
    xs[2][2] = __ldg(lrowC + l2);  xs[2][3] = __ldg(lrowC + l3);

    const int bn = b * NN + quad * 4;
    float4 tbs[4];
    tbs[0] = __ldg(tboxes + bn + 0);
    tbs[1] = __ldg(tboxes + bn + 1);
    tbs[2] = __ldg(tboxes + bn + 2);
    tbs[3] = __ldg(tboxes + bn + 3);

    float4 pbs[3];
    pbs[0] = __ldg(pboxes + bq0);
    pbs[1] = __ldg(pboxes + bq0 + 1);
    pbs[2] = __ldg(pboxes + bq0 + 2);

    // target xyxy + areas (shared by all 3 rows)
    float txy[4][4], ta[4];
    #pragma unroll
    for (int i = 0; i < 4; i++) {
        txy[i][0] = tbs[i].x - 0.5f * tbs[i].z;
        txy[i][1] = tbs[i].y - 0.5f * tbs[i].w;
        txy[i][2] = tbs[i].x + 0.5f * tbs[i].z;
        txy[i][3] = tbs[i].y + 0.5f * tbs[i].w;
        ta[i] = tbs[i].z * tbs[i].w;
    }

    #pragma unroll
    for (int rr = 0; rr < 3; rr++) {
        const float4 pb = pbs[rr];
        const float px0 = pb.x - 0.5f * pb.z, px1 = pb.x + 0.5f * pb.z;
        const float py0 = pb.y - 0.5f * pb.w, py1 = pb.y + 0.5f * pb.w;
        const float area1 = pb.z * pb.w;

        float4 res;
        float* resp = &res.x;

        #pragma unroll
        for (int i = 0; i < 4; i++) {
            float x = xs[rr][i];

            // focal class cost (3 MUFU)
            float e  = __expf(-x);
            float sg = 1.0f + e;
            float p  = __fdividef(1.0f, sg);
            float L  = __logf(sg);
            float logp   = fmaxf(-L,     -18.420681f);
            float log1mp = fmaxf(-x - L, -18.420681f);
            float omp = 1.0f - p;
            float cls = -0.25f * omp * omp * logp + 0.75f * p * p * log1mp;

            // L1 box cost
            float l1 = fabsf(pb.x - tbs[i].x) + fabsf(pb.y - tbs[i].y)
                     + fabsf(pb.z - tbs[i].z) + fabsf(pb.w - tbs[i].w);

            // GIoU (1 MUFU)
            float wi = fmaxf(fminf(px1, txy[i][2]) - fmaxf(px0, txy[i][0]), 0.0f);
            float hi = fmaxf(fminf(py1, txy[i][3]) - fmaxf(py0, txy[i][1]), 0.0f);
            float inter = wi * hi;
            float uni   = area1 + ta[i] - inter;
            float wc = fmaxf(px1, txy[i][2]) - fminf(px0, txy[i][0]);
            float hc = fmaxf(py1, txy[i][3]) - fminf(py0, txy[i][1]);
            float ac = wc * hc;
            float num  = ac * (inter - uni) + uni * uni;
            float giou = num * __fdividef(1.0f, uni * ac);

            resp[i] = 2.0f * cls + 5.0f * l1 - 2.0f * giou;
        }

        // row*NN is 16B-aligned (NN=100 -> 25 float4 per row)
        out4[(bq0 + rr) * NQUAD + quad] = res;
    }
}

extern "C" void kernel_launch(void* const* d_in, const int* in_sizes, int n_in,
                              void* d_out, int out_size)
{
    const float*  logits  = (const float*)d_in[0];
    const float4* pboxes  = (const float4*)d_in[1];
    const int4*   labels4 = (const int4*)d_in[2];
    const float4* tboxes  = (const float4*)d_in[3];
    float4* out4 = (float4*)d_out;

    const int threads = 128;
    const int blocks  = (TOTALT + threads - 1) / threads;   // 469
    matcher_cost_kernel<<<blocks, threads>>>(logits, pboxes, labels4, tboxes, out4);
}